// round 4
// baseline (speedup 1.0000x reference)
#include <cuda_runtime.h>
#include <cuda_fp16.h>
#include <cstdint>

#define N_PTS 100000
#define KNN   16
#define CIN   64
#define CMID  64
#define COUT  128
#define NK    (N_PTS * KNN)
#define EPSB  1e-5f

// ---------------- scratch (static device memory; no dynamic alloc) ----------
__device__ int    g_counts[N_PTS];
__device__ float  g_y1[(size_t)N_PTS * CMID];   // pre-BN layer-1 output (fp32)
__device__ __half g_z[(size_t)N_PTS * COUT];    // pre-BN layer-2 output (fp16)
__device__ float  g_stats1[2 * CMID];           // weighted sum, sumsq
__device__ float  g_stats2[2 * COUT];

// ---------------- packed f32x2 helpers --------------------------------------
__device__ __forceinline__ float2 unpack2(unsigned long long v) {
    float2 r;
    asm("mov.b64 {%0, %1}, %2;" : "=f"(r.x), "=f"(r.y) : "l"(v));
    return r;
}
__device__ __forceinline__ void fma2(unsigned long long& d,
                                     unsigned long long a,
                                     unsigned long long b) {
    asm("fma.rn.f32x2 %0, %1, %2, %0;" : "+l"(d) : "l"(a), "l"(b));
}

// ---------------- kernels ----------------------------------------------------
__global__ void zero_kernel() {
    int i = blockIdx.x * blockDim.x + threadIdx.x;
    if (i < N_PTS) g_counts[i] = 0;
    if (i < 2 * CMID) g_stats1[i] = 0.f;
    if (i < 2 * COUT) g_stats2[i] = 0.f;
}

__global__ void count_kernel(const int4* __restrict__ idx4) {
    int i = blockIdx.x * blockDim.x + threadIdx.x;
    if (i < NK / 4) {
        int4 v = idx4[i];
        atomicAdd(&g_counts[v.x], 1);
        atomicAdd(&g_counts[v.y], 1);
        atomicAdd(&g_counts[v.z], 1);
        atomicAdd(&g_counts[v.w], 1);
    }
}

// GEMM1: y1 = feat @ W1 + b1 ; weighted BN1 stats.
// Tile 64 rows x 64 cols, 256 threads (16x16), thread 4x4.
// A stored in smem pre-duplicated as float2(a,a), layout [k][row].
__global__ __launch_bounds__(256) void gemm1_kernel(const float* __restrict__ feat,
                                                    const float* __restrict__ W1,
                                                    const float* __restrict__ b1) {
    __shared__ float2 As2[64 * 64];  // [k][row], 32 KB
    __shared__ float  Ws[64 * 64];   // [k][col], 16 KB
    const int tid = threadIdx.x;
    const int tx = tid & 15, ty = tid >> 4;
    const int row0 = blockIdx.x * 64;

#pragma unroll
    for (int it = 0; it < 4; it++) {
        int f = tid + it * 256;
        ((float4*)Ws)[f] = ((const float4*)W1)[f];
    }
#pragma unroll
    for (int it = 0; it < 4; it++) {
        int f = tid + it * 256;            // [0, 1024)
        int r = f >> 4, k4 = f & 15;
        int grow = row0 + r;
        float4 v = (grow < N_PTS) ? ((const float4*)feat)[grow * 16 + k4]
                                  : make_float4(0.f, 0.f, 0.f, 0.f);
        As2[(k4 * 4 + 0) * 64 + r] = make_float2(v.x, v.x);
        As2[(k4 * 4 + 1) * 64 + r] = make_float2(v.y, v.y);
        As2[(k4 * 4 + 2) * 64 + r] = make_float2(v.z, v.z);
        As2[(k4 * 4 + 3) * 64 + r] = make_float2(v.w, v.w);
    }
    __syncthreads();

    unsigned long long acc[4][2];
#pragma unroll
    for (int i = 0; i < 4; i++) { acc[i][0] = 0ull; acc[i][1] = 0ull; }

#pragma unroll
    for (int k = 0; k < 64; k++) {
        const ulonglong2 bv = *(const ulonglong2*)&Ws[k * 64 + tx * 4];
#pragma unroll
        for (int i = 0; i < 4; i++) {
            unsigned long long ad =
                *(const unsigned long long*)&As2[k * 64 + ty * 4 + i];
            fma2(acc[i][0], ad, bv.x);
            fma2(acc[i][1], ad, bv.y);
        }
    }

    const float4 bias = *(const float4*)&b1[tx * 4];
    float ws[4] = {0.f, 0.f, 0.f, 0.f}, wq[4] = {0.f, 0.f, 0.f, 0.f};
#pragma unroll
    for (int i = 0; i < 4; i++) {
        int grow = row0 + ty * 4 + i;
        float2 lo = unpack2(acc[i][0]);
        float2 hi = unpack2(acc[i][1]);
        float y0 = lo.x + bias.x, y1v = lo.y + bias.y;
        float y2v = hi.x + bias.z, y3 = hi.y + bias.w;
        if (grow < N_PTS) {
            *(float4*)&g_y1[(size_t)grow * 64 + tx * 4] = make_float4(y0, y1v, y2v, y3);
            float w = (float)g_counts[grow];
            ws[0] += w * y0;  wq[0] += w * y0 * y0;
            ws[1] += w * y1v; wq[1] += w * y1v * y1v;
            ws[2] += w * y2v; wq[2] += w * y2v * y2v;
            ws[3] += w * y3;  wq[3] += w * y3 * y3;
        }
    }
    __syncthreads();
    float* red = (float*)As2;
#pragma unroll
    for (int j = 0; j < 4; j++) {
        red[ty * 64 + tx * 4 + j] = ws[j];
        red[1024 + ty * 64 + tx * 4 + j] = wq[j];
    }
    __syncthreads();
    if (tid < 64) {
        float s = 0.f, q = 0.f;
#pragma unroll
        for (int t = 0; t < 16; t++) {
            s += red[t * 64 + tid];
            q += red[1024 + t * 64 + tid];
        }
        atomicAdd(&g_stats1[tid], s);
        atomicAdd(&g_stats1[64 + tid], q);
    }
}

// GEMM2: h = relu(bn1(y1)) (BN1 folded from g_stats1 in-prologue);
// y2 = h @ W2 + b2 ; weighted BN2 stats; y2 stored pre-BN as fp16 in g_z.
// Tile 64 rows x 128 cols, 256 threads (16x16), thread 4x8.
__global__ __launch_bounds__(256) void gemm2_kernel(const float* __restrict__ W2,
                                                    const float* __restrict__ b2,
                                                    const float* __restrict__ gamma1,
                                                    const float* __restrict__ beta1) {
    __shared__ float2 As2[64 * 64];   // [k][row], 32 KB
    __shared__ float  Ws[64 * 128];   // [k][col], 32 KB
    __shared__ float  sb1s[128];      // folded BN1 scale/bias
    const int tid = threadIdx.x;
    const int tx = tid & 15, ty = tid >> 4;
    const int row0 = blockIdx.x * 64;

    if (tid < 64) {
        const float inv_m = 1.0f / (float)NK;
        float mean = g_stats1[tid] * inv_m;
        float var = g_stats1[64 + tid] * inv_m - mean * mean;
        float sc = gamma1[tid] * rsqrtf(var + EPSB);
        sb1s[tid] = sc;
        sb1s[64 + tid] = beta1[tid] - mean * sc;
    }
#pragma unroll
    for (int it = 0; it < 8; it++) {
        int f = tid + it * 256;
        ((float4*)Ws)[f] = ((const float4*)W2)[f];
    }
    __syncthreads();   // sb1s ready before A-tile transform

#pragma unroll
    for (int it = 0; it < 4; it++) {
        int f = tid + it * 256;
        int r = f >> 4, k4 = f & 15;
        int grow = row0 + r;
        float4 v = (grow < N_PTS) ? ((const float4*)g_y1)[grow * 16 + k4]
                                  : make_float4(0.f, 0.f, 0.f, 0.f);
        float4 s = *(const float4*)&sb1s[k4 * 4];
        float4 bb = *(const float4*)&sb1s[64 + k4 * 4];
        v.x = fmaxf(fmaf(v.x, s.x, bb.x), 0.f);
        v.y = fmaxf(fmaf(v.y, s.y, bb.y), 0.f);
        v.z = fmaxf(fmaf(v.z, s.z, bb.z), 0.f);
        v.w = fmaxf(fmaf(v.w, s.w, bb.w), 0.f);
        As2[(k4 * 4 + 0) * 64 + r] = make_float2(v.x, v.x);
        As2[(k4 * 4 + 1) * 64 + r] = make_float2(v.y, v.y);
        As2[(k4 * 4 + 2) * 64 + r] = make_float2(v.z, v.z);
        As2[(k4 * 4 + 3) * 64 + r] = make_float2(v.w, v.w);
    }
    __syncthreads();

    unsigned long long acc[4][4];
#pragma unroll
    for (int i = 0; i < 4; i++)
#pragma unroll
        for (int j = 0; j < 4; j++) acc[i][j] = 0ull;

#pragma unroll
    for (int k = 0; k < 64; k++) {
        const ulonglong2 b0 = *(const ulonglong2*)&Ws[k * 128 + tx * 8];
        const ulonglong2 b1v = *(const ulonglong2*)&Ws[k * 128 + tx * 8 + 4];
#pragma unroll
        for (int i = 0; i < 4; i++) {
            unsigned long long ad =
                *(const unsigned long long*)&As2[k * 64 + ty * 4 + i];
            fma2(acc[i][0], ad, b0.x);
            fma2(acc[i][1], ad, b0.y);
            fma2(acc[i][2], ad, b1v.x);
            fma2(acc[i][3], ad, b1v.y);
        }
    }

    const float4 biasA = *(const float4*)&b2[tx * 8];
    const float4 biasB = *(const float4*)&b2[tx * 8 + 4];
    float ws[8], wq[8];
#pragma unroll
    for (int j = 0; j < 8; j++) { ws[j] = 0.f; wq[j] = 0.f; }
#pragma unroll
    for (int i = 0; i < 4; i++) {
        int grow = row0 + ty * 4 + i;
        float2 p0 = unpack2(acc[i][0]);
        float2 p1 = unpack2(acc[i][1]);
        float2 p2 = unpack2(acc[i][2]);
        float2 p3 = unpack2(acc[i][3]);
        float y[8];
        y[0] = p0.x + biasA.x; y[1] = p0.y + biasA.y;
        y[2] = p1.x + biasA.z; y[3] = p1.y + biasA.w;
        y[4] = p2.x + biasB.x; y[5] = p2.y + biasB.y;
        y[6] = p3.x + biasB.z; y[7] = p3.y + biasB.w;
        if (grow < N_PTS) {
            __half2 h[4];
#pragma unroll
            for (int j = 0; j < 4; j++)
                h[j] = __floats2half2_rn(y[2 * j], y[2 * j + 1]);
            *(uint4*)&g_z[(size_t)grow * 128 + tx * 8] = *(uint4*)h;
            float w = (float)g_counts[grow];
#pragma unroll
            for (int j = 0; j < 8; j++) {
                ws[j] += w * y[j];
                wq[j] += w * y[j] * y[j];
            }
        }
    }
    __syncthreads();
    float* red = (float*)As2;   // 8192 floats available, need 4096
#pragma unroll
    for (int j = 0; j < 8; j++) {
        red[ty * 128 + tx * 8 + j] = ws[j];
        red[2048 + ty * 128 + tx * 8 + j] = wq[j];
    }
    __syncthreads();
    if (tid < 128) {
        float s = 0.f, q = 0.f;
#pragma unroll
        for (int t = 0; t < 16; t++) {
            s += red[t * 128 + tid];
            q += red[2048 + t * 128 + tid];
        }
        atomicAdd(&g_stats2[tid], s);
        atomicAdd(&g_stats2[128 + tid], q);
    }
}

// Final gather + max/min-pool over pre-BN fp16 table, then folded BN2
// affine + ReLU (computed per-thread from g_stats2). One warp = TWO points:
// lanes 0-15 -> point 2w, lanes 16-31 -> point 2w+1; each lane owns 8 channels.
__global__ __launch_bounds__(256) void gather_max_kernel(
    const int* __restrict__ idx, const float* __restrict__ gamma2,
    const float* __restrict__ beta2, float* __restrict__ out) {
    int warp = (blockIdx.x * blockDim.x + threadIdx.x) >> 5;
    int lane = threadIdx.x & 31;
    int p = warp * 2 + (lane >> 4);
    if (p >= N_PTS) return;
    int half_lane = lane & 15;
    int c0 = half_lane * 8;

    int myidx = idx[p * 16 + half_lane];

    __half2 mx[4], mn[4];
#pragma unroll
    for (int j = 0; j < 4; j++) {
        mx[j] = __floats2half2_rn(-65504.f, -65504.f);
        mn[j] = __floats2half2_rn(65504.f, 65504.f);
    }

#pragma unroll
    for (int k = 0; k < 16; k++) {
        int r = __shfl_sync(0xffffffffu, myidx, (lane & 16) + k);
        uint4 raw = *(const uint4*)&g_z[(size_t)r * 128 + c0];
        __half2 v[4];
        *(uint4*)v = raw;
        mx[0] = __hmax2(mx[0], v[0]); mn[0] = __hmin2(mn[0], v[0]);
        mx[1] = __hmax2(mx[1], v[1]); mn[1] = __hmin2(mn[1], v[1]);
        mx[2] = __hmax2(mx[2], v[2]); mn[2] = __hmin2(mn[2], v[2]);
        mx[3] = __hmax2(mx[3], v[3]); mn[3] = __hmin2(mn[3], v[3]);
    }

    // folded BN2 for this thread's 8 channels
    const float inv_m = 1.0f / (float)NK;
    float4 sum0 = *(const float4*)&g_stats2[c0];
    float4 sum1 = *(const float4*)&g_stats2[c0 + 4];
    float4 sq0 = *(const float4*)&g_stats2[128 + c0];
    float4 sq1 = *(const float4*)&g_stats2[128 + c0 + 4];
    float4 gm0 = *(const float4*)&gamma2[c0];
    float4 gm1 = *(const float4*)&gamma2[c0 + 4];
    float4 bt0 = *(const float4*)&beta2[c0];
    float4 bt1 = *(const float4*)&beta2[c0 + 4];
    float sm[8] = {sum0.x, sum0.y, sum0.z, sum0.w, sum1.x, sum1.y, sum1.z, sum1.w};
    float sq[8] = {sq0.x, sq0.y, sq0.z, sq0.w, sq1.x, sq1.y, sq1.z, sq1.w};
    float gm[8] = {gm0.x, gm0.y, gm0.z, gm0.w, gm1.x, gm1.y, gm1.z, gm1.w};
    float bt[8] = {bt0.x, bt0.y, bt0.z, bt0.w, bt1.x, bt1.y, bt1.z, bt1.w};

    float o[8];
#pragma unroll
    for (int j = 0; j < 8; j++) {
        float mean = sm[j] * inv_m;
        float var = sq[j] * inv_m - mean * mean;
        float sc = gm[j] * rsqrtf(var + EPSB);
        float bi = bt[j] - mean * sc;
        float2 fx = __half22float2(mx[j >> 1]);
        float2 fn = __half22float2(mn[j >> 1]);
        float vx = (j & 1) ? fx.y : fx.x;
        float vn = (j & 1) ? fn.y : fn.x;
        float m = (sc >= 0.f) ? vx : vn;
        o[j] = fmaxf(fmaf(sc, m, bi), 0.f);
    }
    size_t off = (size_t)p * 128 + c0;
    *(float4*)&out[off]     = make_float4(o[0], o[1], o[2], o[3]);
    *(float4*)&out[off + 4] = make_float4(o[4], o[5], o[6], o[7]);
}

// ---------------- launch ------------------------------------------------------
extern "C" void kernel_launch(void* const* d_in, const int* in_sizes, int n_in,
                              void* d_out, int out_size) {
    const float* feat = (const float*)d_in[0];
    const int* idx = (const int*)d_in[1];
    const float* W1 = (const float*)d_in[2];
    const float* b1 = (const float*)d_in[3];
    const float* g1 = (const float*)d_in[4];
    const float* be1 = (const float*)d_in[5];
    const float* W2 = (const float*)d_in[6];
    const float* b2 = (const float*)d_in[7];
    const float* g2 = (const float*)d_in[8];
    const float* be2 = (const float*)d_in[9];
    float* out = (float*)d_out;

    zero_kernel<<<(N_PTS + 255) / 256, 256>>>();
    count_kernel<<<(NK / 4 + 255) / 256, 256>>>((const int4*)idx);
    gemm1_kernel<<<(N_PTS + 63) / 64, 256>>>(feat, W1, b1);
    gemm2_kernel<<<(N_PTS + 63) / 64, 256>>>(W2, b2, g1, be1);
    gather_max_kernel<<<(N_PTS * 16 + 255) / 256, 256>>>(idx, g2, be2, out);
}

// round 5
// speedup vs baseline: 1.5318x; 1.5318x over previous
#include <cuda_runtime.h>
#include <cuda_fp16.h>
#include <cstdint>

#define N_PTS 100000
#define KNN   16
#define CIN   64
#define CMID  64
#define COUT  128
#define NK    (N_PTS * KNN)
#define EPSB  1e-5f

// ---------------- scratch (static device memory; no dynamic alloc) ----------
__device__ int    g_counts[N_PTS];
__device__ float  g_y1[(size_t)N_PTS * CMID];   // pre-BN layer-1 output (fp32)
__device__ __half g_z[(size_t)N_PTS * COUT];    // pre-BN layer-2 output (fp16)
__device__ float  g_stats1[2 * CMID];           // weighted sum, sumsq
__device__ float  g_stats2[2 * COUT];

// ---------------- packed f32x2 helpers --------------------------------------
__device__ __forceinline__ unsigned long long pack2s(float a) {
    unsigned long long r;
    asm("mov.b64 %0, {%1, %1};" : "=l"(r) : "f"(a));
    return r;
}
__device__ __forceinline__ float2 unpack2(unsigned long long v) {
    float2 r;
    asm("mov.b64 {%0, %1}, %2;" : "=f"(r.x), "=f"(r.y) : "l"(v));
    return r;
}
__device__ __forceinline__ void fma2(unsigned long long& d,
                                     unsigned long long a,
                                     unsigned long long b) {
    asm("fma.rn.f32x2 %0, %1, %2, %0;" : "+l"(d) : "l"(a), "l"(b));
}
__device__ __forceinline__ float felem(const float4& v, int k) {
    return (k == 0) ? v.x : (k == 1) ? v.y : (k == 2) ? v.z : v.w;
}

// ---------------- kernels ----------------------------------------------------
__global__ void zero_kernel() {
    int i = blockIdx.x * blockDim.x + threadIdx.x;
    if (i < N_PTS) g_counts[i] = 0;
    if (i < 2 * CMID) g_stats1[i] = 0.f;
    if (i < 2 * COUT) g_stats2[i] = 0.f;
}

__global__ void count_kernel(const int4* __restrict__ idx4) {
    int i = blockIdx.x * blockDim.x + threadIdx.x;
    if (i < NK / 4) {
        int4 v = idx4[i];
        atomicAdd(&g_counts[v.x], 1);
        atomicAdd(&g_counts[v.y], 1);
        atomicAdd(&g_counts[v.z], 1);
        atomicAdd(&g_counts[v.w], 1);
    }
}

// GEMM1: y1 = feat @ W1 + b1 ; weighted BN1 stats.
// Block: 128 rows x 64 cols, 256 threads as 8(tx) x 32(ty).
// Thread tile: 4 rows (ty*4..+3) x 8 cols ({tx*4..+3, 32+tx*4..+3}).
// A smem [row][k] (natural), B smem [k][col] (natural W layout).
__global__ __launch_bounds__(256) void gemm1_kernel(const float* __restrict__ feat,
                                                    const float* __restrict__ W1,
                                                    const float* __restrict__ b1) {
    __shared__ float As[128 * 64];  // 32 KB
    __shared__ float Bs[64 * 64];   // 16 KB
    const int tid = threadIdx.x;
    const int tx = tid & 7, ty = tid >> 3;
    const int row0 = blockIdx.x * 128;

#pragma unroll
    for (int it = 0; it < 4; it++) {
        int f = tid + it * 256;
        ((float4*)Bs)[f] = ((const float4*)W1)[f];
    }
#pragma unroll
    for (int it = 0; it < 8; it++) {
        int f = tid + it * 256;          // [0, 2048)
        int r = f >> 4, k4 = f & 15;
        int grow = row0 + r;
        float4 v = (grow < N_PTS) ? ((const float4*)feat)[grow * 16 + k4]
                                  : make_float4(0.f, 0.f, 0.f, 0.f);
        ((float4*)As)[r * 16 + k4] = v;
    }
    __syncthreads();

    unsigned long long acc[4][4];
#pragma unroll
    for (int i = 0; i < 4; i++)
#pragma unroll
        for (int j = 0; j < 4; j++) acc[i][j] = 0ull;

#pragma unroll
    for (int kk = 0; kk < 64; kk += 4) {
        float4 a[4];
#pragma unroll
        for (int i = 0; i < 4; i++)
            a[i] = *(const float4*)&As[(ty * 4 + i) * 64 + kk];
#pragma unroll
        for (int kq = 0; kq < 4; kq++) {
            const ulonglong2 bA = *(const ulonglong2*)&Bs[(kk + kq) * 64 + tx * 4];
            const ulonglong2 bB = *(const ulonglong2*)&Bs[(kk + kq) * 64 + 32 + tx * 4];
#pragma unroll
            for (int i = 0; i < 4; i++) {
                unsigned long long ad = pack2s(felem(a[i], kq));
                fma2(acc[i][0], ad, bA.x);
                fma2(acc[i][1], ad, bA.y);
                fma2(acc[i][2], ad, bB.x);
                fma2(acc[i][3], ad, bB.y);
            }
        }
    }

    const float4 biasA = *(const float4*)&b1[tx * 4];
    const float4 biasB = *(const float4*)&b1[32 + tx * 4];
    float ws[8], wq[8];
#pragma unroll
    for (int j = 0; j < 8; j++) { ws[j] = 0.f; wq[j] = 0.f; }
#pragma unroll
    for (int i = 0; i < 4; i++) {
        int grow = row0 + ty * 4 + i;
        if (grow >= N_PTS) continue;
        float2 p0 = unpack2(acc[i][0]);
        float2 p1 = unpack2(acc[i][1]);
        float2 p2 = unpack2(acc[i][2]);
        float2 p3 = unpack2(acc[i][3]);
        float y[8];
        y[0] = p0.x + biasA.x; y[1] = p0.y + biasA.y;
        y[2] = p1.x + biasA.z; y[3] = p1.y + biasA.w;
        y[4] = p2.x + biasB.x; y[5] = p2.y + biasB.y;
        y[6] = p3.x + biasB.z; y[7] = p3.y + biasB.w;
        *(float4*)&g_y1[(size_t)grow * 64 + tx * 4] = make_float4(y[0], y[1], y[2], y[3]);
        *(float4*)&g_y1[(size_t)grow * 64 + 32 + tx * 4] = make_float4(y[4], y[5], y[6], y[7]);
        float w = (float)g_counts[grow];
#pragma unroll
        for (int j = 0; j < 8; j++) {
            ws[j] += w * y[j];
            wq[j] += w * y[j] * y[j];
        }
    }
    __syncthreads();
    float* red = As;  // 8192 floats available, need 4096
#pragma unroll
    for (int j = 0; j < 4; j++) {
        red[ty * 64 + tx * 4 + j] = ws[j];
        red[ty * 64 + 32 + tx * 4 + j] = ws[4 + j];
        red[2048 + ty * 64 + tx * 4 + j] = wq[j];
        red[2048 + ty * 64 + 32 + tx * 4 + j] = wq[4 + j];
    }
    __syncthreads();
    if (tid < 64) {
        float s = 0.f, q = 0.f;
#pragma unroll
        for (int t = 0; t < 32; t++) {
            s += red[t * 64 + tid];
            q += red[2048 + t * 64 + tid];
        }
        atomicAdd(&g_stats1[tid], s);
        atomicAdd(&g_stats1[64 + tid], q);
    }
}

// GEMM2: h = relu(bn1(y1)) (BN1 folded in-prologue from g_stats1);
// y2 = h @ W2 + b2, stored pre-BN as fp16; weighted BN2 stats.
// Block: 128 rows x 128 cols, 256 threads as 16(tx) x 16(ty).
// Thread tile: 8 rows ({ty*4..+3, 64+ty*4..+3}) x 8 cols ({tx*4..+3, 64+tx*4..+3}).
__global__ __launch_bounds__(256) void gemm2_kernel(const float* __restrict__ W2,
                                                    const float* __restrict__ b2,
                                                    const float* __restrict__ gamma1,
                                                    const float* __restrict__ beta1) {
    __shared__ float As[128 * 64];   // 32 KB, [row][k]
    __shared__ float Bs[64 * 128];   // 32 KB, [k][col]
    __shared__ float sb1s[128];
    const int tid = threadIdx.x;
    const int tx = tid & 15, ty = tid >> 4;
    const int row0 = blockIdx.x * 128;

    if (tid < 64) {
        const float inv_m = 1.0f / (float)NK;
        float mean = g_stats1[tid] * inv_m;
        float var = g_stats1[64 + tid] * inv_m - mean * mean;
        float sc = gamma1[tid] * rsqrtf(var + EPSB);
        sb1s[tid] = sc;
        sb1s[64 + tid] = beta1[tid] - mean * sc;
    }
#pragma unroll
    for (int it = 0; it < 8; it++) {
        int f = tid + it * 256;
        ((float4*)Bs)[f] = ((const float4*)W2)[f];
    }
    __syncthreads();   // sb1s ready

#pragma unroll
    for (int it = 0; it < 8; it++) {
        int f = tid + it * 256;          // [0, 2048)
        int r = f >> 4, k4 = f & 15;
        int grow = row0 + r;
        float4 v = (grow < N_PTS) ? ((const float4*)g_y1)[grow * 16 + k4]
                                  : make_float4(0.f, 0.f, 0.f, 0.f);
        float4 s = *(const float4*)&sb1s[k4 * 4];
        float4 bb = *(const float4*)&sb1s[64 + k4 * 4];
        v.x = fmaxf(fmaf(v.x, s.x, bb.x), 0.f);
        v.y = fmaxf(fmaf(v.y, s.y, bb.y), 0.f);
        v.z = fmaxf(fmaf(v.z, s.z, bb.z), 0.f);
        v.w = fmaxf(fmaf(v.w, s.w, bb.w), 0.f);
        ((float4*)As)[r * 16 + k4] = v;
    }
    __syncthreads();

    unsigned long long acc[8][4];
#pragma unroll
    for (int i = 0; i < 8; i++)
#pragma unroll
        for (int j = 0; j < 4; j++) acc[i][j] = 0ull;

#pragma unroll
    for (int kk = 0; kk < 64; kk += 4) {
        float4 a[8];
#pragma unroll
        for (int i = 0; i < 4; i++) {
            a[i]     = *(const float4*)&As[(ty * 4 + i) * 64 + kk];
            a[4 + i] = *(const float4*)&As[(64 + ty * 4 + i) * 64 + kk];
        }
#pragma unroll
        for (int kq = 0; kq < 4; kq++) {
            const ulonglong2 bA = *(const ulonglong2*)&Bs[(kk + kq) * 128 + tx * 4];
            const ulonglong2 bB = *(const ulonglong2*)&Bs[(kk + kq) * 128 + 64 + tx * 4];
#pragma unroll
            for (int i = 0; i < 8; i++) {
                unsigned long long ad = pack2s(felem(a[i], kq));
                fma2(acc[i][0], ad, bA.x);
                fma2(acc[i][1], ad, bA.y);
                fma2(acc[i][2], ad, bB.x);
                fma2(acc[i][3], ad, bB.y);
            }
        }
    }

    const float4 biasA = *(const float4*)&b2[tx * 4];
    const float4 biasB = *(const float4*)&b2[64 + tx * 4];
    float ws[8], wq[8];
#pragma unroll
    for (int j = 0; j < 8; j++) { ws[j] = 0.f; wq[j] = 0.f; }
#pragma unroll
    for (int i = 0; i < 8; i++) {
        int grow = row0 + ((i < 4) ? (ty * 4 + i) : (64 + ty * 4 + (i - 4)));
        if (grow >= N_PTS) continue;
        float2 p0 = unpack2(acc[i][0]);
        float2 p1 = unpack2(acc[i][1]);
        float2 p2 = unpack2(acc[i][2]);
        float2 p3 = unpack2(acc[i][3]);
        float y[8];
        y[0] = p0.x + biasA.x; y[1] = p0.y + biasA.y;
        y[2] = p1.x + biasA.z; y[3] = p1.y + biasA.w;
        y[4] = p2.x + biasB.x; y[5] = p2.y + biasB.y;
        y[6] = p3.x + biasB.z; y[7] = p3.y + biasB.w;
        __half2 hA[2], hB[2];
        hA[0] = __floats2half2_rn(y[0], y[1]);
        hA[1] = __floats2half2_rn(y[2], y[3]);
        hB[0] = __floats2half2_rn(y[4], y[5]);
        hB[1] = __floats2half2_rn(y[6], y[7]);
        *(uint2*)&g_z[(size_t)grow * 128 + tx * 4]      = *(uint2*)hA;
        *(uint2*)&g_z[(size_t)grow * 128 + 64 + tx * 4] = *(uint2*)hB;
        float w = (float)g_counts[grow];
#pragma unroll
        for (int j = 0; j < 8; j++) {
            ws[j] += w * y[j];
            wq[j] += w * y[j] * y[j];
        }
    }
    __syncthreads();
    float* red = As;  // 8192 floats, need 2 * 2048
#pragma unroll
    for (int j = 0; j < 4; j++) {
        red[ty * 128 + tx * 4 + j] = ws[j];
        red[ty * 128 + 64 + tx * 4 + j] = ws[4 + j];
        red[2048 + ty * 128 + tx * 4 + j] = wq[j];
        red[2048 + ty * 128 + 64 + tx * 4 + j] = wq[4 + j];
    }
    __syncthreads();
    if (tid < 128) {
        float s = 0.f, q = 0.f;
#pragma unroll
        for (int t = 0; t < 16; t++) {
            s += red[t * 128 + tid];
            q += red[2048 + t * 128 + tid];
        }
        atomicAdd(&g_stats2[tid], s);
        atomicAdd(&g_stats2[128 + tid], q);
    }
}

// Final gather + max/min-pool over pre-BN fp16 table, then folded BN2
// affine + ReLU (per-thread from g_stats2). One warp = TWO points.
__global__ __launch_bounds__(256) void gather_max_kernel(
    const int* __restrict__ idx, const float* __restrict__ gamma2,
    const float* __restrict__ beta2, float* __restrict__ out) {
    int warp = (blockIdx.x * blockDim.x + threadIdx.x) >> 5;
    int lane = threadIdx.x & 31;
    int p = warp * 2 + (lane >> 4);
    if (p >= N_PTS) return;
    int half_lane = lane & 15;
    int c0 = half_lane * 8;

    int myidx = idx[p * 16 + half_lane];

    __half2 mx[4], mn[4];
#pragma unroll
    for (int j = 0; j < 4; j++) {
        mx[j] = __floats2half2_rn(-65504.f, -65504.f);
        mn[j] = __floats2half2_rn(65504.f, 65504.f);
    }

#pragma unroll
    for (int k = 0; k < 16; k++) {
        int r = __shfl_sync(0xffffffffu, myidx, (lane & 16) + k);
        uint4 raw = *(const uint4*)&g_z[(size_t)r * 128 + c0];
        __half2 v[4];
        *(uint4*)v = raw;
        mx[0] = __hmax2(mx[0], v[0]); mn[0] = __hmin2(mn[0], v[0]);
        mx[1] = __hmax2(mx[1], v[1]); mn[1] = __hmin2(mn[1], v[1]);
        mx[2] = __hmax2(mx[2], v[2]); mn[2] = __hmin2(mn[2], v[2]);
        mx[3] = __hmax2(mx[3], v[3]); mn[3] = __hmin2(mn[3], v[3]);
    }

    const float inv_m = 1.0f / (float)NK;
    float4 sum0 = *(const float4*)&g_stats2[c0];
    float4 sum1 = *(const float4*)&g_stats2[c0 + 4];
    float4 sq0 = *(const float4*)&g_stats2[128 + c0];
    float4 sq1 = *(const float4*)&g_stats2[128 + c0 + 4];
    float4 gm0 = *(const float4*)&gamma2[c0];
    float4 gm1 = *(const float4*)&gamma2[c0 + 4];
    float4 bt0 = *(const float4*)&beta2[c0];
    float4 bt1 = *(const float4*)&beta2[c0 + 4];
    float sm[8] = {sum0.x, sum0.y, sum0.z, sum0.w, sum1.x, sum1.y, sum1.z, sum1.w};
    float sq[8] = {sq0.x, sq0.y, sq0.z, sq0.w, sq1.x, sq1.y, sq1.z, sq1.w};
    float gm[8] = {gm0.x, gm0.y, gm0.z, gm0.w, gm1.x, gm1.y, gm1.z, gm1.w};
    float bt[8] = {bt0.x, bt0.y, bt0.z, bt0.w, bt1.x, bt1.y, bt1.z, bt1.w};

    float o[8];
#pragma unroll
    for (int j = 0; j < 8; j++) {
        float mean = sm[j] * inv_m;
        float var = sq[j] * inv_m - mean * mean;
        float sc = gm[j] * rsqrtf(var + EPSB);
        float bi = bt[j] - mean * sc;
        float2 fx = __half22float2(mx[j >> 1]);
        float2 fn = __half22float2(mn[j >> 1]);
        float vx = (j & 1) ? fx.y : fx.x;
        float vn = (j & 1) ? fn.y : fn.x;
        float m = (sc >= 0.f) ? vx : vn;
        o[j] = fmaxf(fmaf(sc, m, bi), 0.f);
    }
    size_t off = (size_t)p * 128 + c0;
    *(float4*)&out[off]     = make_float4(o[0], o[1], o[2], o[3]);
    *(float4*)&out[off + 4] = make_float4(o[4], o[5], o[6], o[7]);
}

// ---------------- launch ------------------------------------------------------
extern "C" void kernel_launch(void* const* d_in, const int* in_sizes, int n_in,
                              void* d_out, int out_size) {
    const float* feat = (const float*)d_in[0];
    const int* idx = (const int*)d_in[1];
    const float* W1 = (const float*)d_in[2];
    const float* b1 = (const float*)d_in[3];
    const float* g1 = (const float*)d_in[4];
    const float* be1 = (const float*)d_in[5];
    const float* W2 = (const float*)d_in[6];
    const float* b2 = (const float*)d_in[7];
    const float* g2 = (const float*)d_in[8];
    const float* be2 = (const float*)d_in[9];
    float* out = (float*)d_out;

    zero_kernel<<<(N_PTS + 255) / 256, 256>>>();
    count_kernel<<<(NK / 4 + 255) / 256, 256>>>((const int4*)idx);
    gemm1_kernel<<<(N_PTS + 127) / 128, 256>>>(feat, W1, b1);
    gemm2_kernel<<<(N_PTS + 127) / 128, 256>>>(W2, b2, g1, be1);
    gather_max_kernel<<<(N_PTS * 16 + 255) / 256, 256>>>(idx, g2, be2, out);
}